// round 4
// baseline (speedup 1.0000x reference)
#include <cuda_runtime.h>
#include <cuda_bf16.h>

// Problem constants
#define B_    64
#define N_    200000
#define V_    64          // 4^3 voxels
#define CLS_  40

// Histogram geometry: 16 chunks per batch, 256 threads/block.
// 200000/16 = 12500 points/block = 3125 groups of 4 points (exact).
#define CHUNKS_ 16
#define PTS_    (N_ / CHUNKS_)          // 12500
#define GRPS_   (PTS_ / 4)              // 3125
#define TPB_    256
#define FULL_ITERS_ (GRPS_ / TPB_)      // 12
#define TAIL_       (GRPS_ - FULL_ITERS_ * TPB_)  // 53

// Scratch (no cudaMalloc allowed): per-(batch,chunk) partial counts, written
// with plain stores (each block owns its slot -> no zeroing kernel needed),
// and per-batch completion counters that self-reset via atomicInc wrap
// (mod CHUNKS_), so the kernel is deterministic across graph replays.
__device__ int g_part[B_ * CHUNKS_][V_];
__device__ unsigned g_done[B_];   // zero-initialized at load; wraps back to 0

__global__ __launch_bounds__(TPB_) void fused_voxel_kernel(
    const float* __restrict__ x,
    const float* __restrict__ W,
    const float* __restrict__ bias,
    float* __restrict__ out)
{
    __shared__ int   sh[V_];
    __shared__ float cf[V_];
    __shared__ unsigned is_last;

    const int b     = blockIdx.y;
    const int chunk = blockIdx.x;
    const int tid   = threadIdx.x;

    if (tid < V_) sh[tid] = 0;
    __syncthreads();

    // This block's contiguous slice: 12500 points * 3 floats (48B groups).
    const float4* __restrict__ base = reinterpret_cast<const float4*>(
        x + ((size_t)b * N_ + (size_t)chunk * PTS_) * 3);

    auto do4 = [&](int g) {
        // 4 points = 12 floats = 3 x LDG.128
        const float4 a = base[g * 3 + 0];
        const float4 c = base[g * 3 + 1];
        const float4 d = base[g * 3 + 2];
        const float px[4] = {a.x, a.w, c.z, d.y};
        const float py[4] = {a.y, c.x, c.w, d.z};
        const float pz[4] = {a.z, c.y, d.x, d.w};
#pragma unroll
        for (int p = 0; p < 4; p++) {
            const int i0 = __float2int_rd(px[p]);
            const int i1 = __float2int_rd(py[p]);
            const int i2 = __float2int_rd(pz[p]);
            // (i0+2)*16 + (i1+2)*4 + (i2+2) folded into +42
            const int bin = i0 * 16 + i1 * 4 + i2 + 42;
            // in-range iff max(|x|,|y|,|z|) < 2 (strict bound drops only
            // measure-zero boundary points; guarantees bin in [0,63])
            const float m = fmaxf(fmaxf(fabsf(px[p]), fabsf(py[p])), fabsf(pz[p]));
            if (m < 2.0f) atomicAdd(&sh[bin], 1);   // predicated ATOMS
        }
    };

#pragma unroll 2
    for (int i = 0; i < FULL_ITERS_; i++) do4(i * TPB_ + tid);
    if (tid < TAIL_) do4(FULL_ITERS_ * TPB_ + tid);

    __syncthreads();

    // Publish this block's partial counts (plain stores; block owns the slot).
    if (tid < V_) g_part[b * CHUNKS_ + chunk][tid] = sh[tid];
    __threadfence();   // release: partials visible before the counter bump

    if (tid == 0)
        is_last = (atomicInc(&g_done[b], CHUNKS_ - 1) == CHUNKS_ - 1) ? 1u : 0u;
    __syncthreads();
    if (!is_last) return;

    // ---- Epilogue: last block of this batch reduces + GEMV ----
    __threadfence();   // acquire: order counter read before partial reads

    if (tid < V_) {
        int s = 0;
#pragma unroll
        for (int c = 0; c < CHUNKS_; c++)
            s += __ldcg(&g_part[b * CHUNKS_ + c][tid]);   // L2-coherent reads
        cf[tid] = (float)s;
    }
    __syncthreads();

    if (tid < CLS_) {
        float tot = 0.f;
#pragma unroll
        for (int v = 0; v < V_; v++) tot += cf[v];   // exact: integers < 2^24
        float acc = 0.f;
#pragma unroll
        for (int v = 0; v < V_; v++) acc += cf[v] * W[tid * V_ + v];
        out[b * CLS_ + tid] = acc / tot + bias[tid];
    }
}

extern "C" void kernel_launch(void* const* d_in, const int* in_sizes, int n_in,
                              void* d_out, int out_size) {
    const float* x    = (const float*)d_in[0];   // [B, N, 3] f32
    const float* W    = (const float*)d_in[1];   // [CLASSES, V] f32
    const float* bias = (const float*)d_in[2];   // [CLASSES] f32
    float* out = (float*)d_out;                  // [B, CLASSES] f32

    fused_voxel_kernel<<<dim3(CHUNKS_, B_), TPB_>>>(x, W, bias, out);
}

// round 5
// speedup vs baseline: 1.1159x; 1.1159x over previous
#include <cuda_runtime.h>
#include <cuda_bf16.h>

// Problem constants
#define B_    64
#define N_    200000
#define V_    64          // 4^3 voxels
#define CLS_  40
#define BINS_ 65          // 64 real + 1 dummy (out-of-range) -> branchless SEL

// Histogram geometry: 40 chunks per batch for fine-grained load balance.
// 200000/40 = 5000 points/block = 1250 groups of 4 points (exact).
#define CHUNKS_ 40
#define PTS_    (N_ / CHUNKS_)          // 5000
#define GRPS_   (PTS_ / 4)              // 1250
#define TPB_    256
#define FULL_ITERS_ (GRPS_ / TPB_)      // 4
#define TAIL_       (GRPS_ - FULL_ITERS_ * TPB_)  // 226

// Scratch (no cudaMalloc allowed): per-(batch,chunk) partial counts, written
// with plain stores (each block owns its slot -> nothing to pre-zero), and
// per-batch completion counters that self-reset via atomicInc wrap
// (mod CHUNKS_), so the kernel is deterministic across graph replays.
__device__ int g_part[B_ * CHUNKS_][V_];
__device__ unsigned g_done[B_];   // zero-initialized at load; wraps back to 0

__global__ __launch_bounds__(TPB_) void fused_voxel_kernel(
    const float* __restrict__ x,
    const float* __restrict__ W,
    const float* __restrict__ bias,
    float* __restrict__ out)
{
    __shared__ int   sh[BINS_];
    __shared__ float cf[V_];
    __shared__ unsigned is_last;

    const int b     = blockIdx.y;
    const int chunk = blockIdx.x;
    const int tid   = threadIdx.x;

    if (tid < BINS_) sh[tid] = 0;
    __syncthreads();

    // This block's contiguous slice: 5000 points * 3 floats (48B groups).
    const float4* __restrict__ base = reinterpret_cast<const float4*>(
        x + ((size_t)b * N_ + (size_t)chunk * PTS_) * 3);

    auto do4 = [&](int g) {
        // 4 points = 12 floats = 3 x LDG.128 (streaming: no reuse)
        const float4 a = __ldcs(&base[g * 3 + 0]);
        const float4 c = __ldcs(&base[g * 3 + 1]);
        const float4 d = __ldcs(&base[g * 3 + 2]);
        const float px[4] = {a.x, a.w, c.z, d.y};
        const float py[4] = {a.y, c.x, c.w, d.z};
        const float pz[4] = {a.z, c.y, d.x, d.w};
#pragma unroll
        for (int p = 0; p < 4; p++) {
            const int i0 = __float2int_rd(px[p]);
            const int i1 = __float2int_rd(py[p]);
            const int i2 = __float2int_rd(pz[p]);
            // (i0+2)*16 + (i1+2)*4 + (i2+2) folded into +42
            int bin = i0 * 16 + i1 * 4 + i2 + 42;
            // in-range iff max(|x|,|y|,|z|) < 2; branchless: SEL to dummy bin.
            // (strict bound drops only measure-zero boundary points and
            // guarantees bin in [0,63] for in-range points)
            const float m = fmaxf(fmaxf(fabsf(px[p]), fabsf(py[p])), fabsf(pz[p]));
            bin = (m < 2.0f) ? bin : 64;
            atomicAdd(&sh[bin], 1);          // unconditional ATOMS, no branch
        }
    };

#pragma unroll 2
    for (int i = 0; i < FULL_ITERS_; i++) do4(i * TPB_ + tid);
    if (tid < TAIL_) do4(FULL_ITERS_ * TPB_ + tid);

    __syncthreads();

    // Publish this block's partial counts (plain stores; block owns the slot).
    if (tid < V_) g_part[b * CHUNKS_ + chunk][tid] = sh[tid];   // dummy bin dropped
    __threadfence();   // release: partials visible before the counter bump

    if (tid == 0)
        is_last = (atomicInc(&g_done[b], CHUNKS_ - 1) == CHUNKS_ - 1) ? 1u : 0u;
    __syncthreads();
    if (!is_last) return;

    // ---- Epilogue: last block of this batch reduces + GEMV ----
    __threadfence();   // acquire: order counter read before partial reads

    if (tid < V_) {
        int s = 0;
#pragma unroll
        for (int c = 0; c < CHUNKS_; c++)
            s += __ldcg(&g_part[b * CHUNKS_ + c][tid]);   // L2-coherent reads
        cf[tid] = (float)s;
    }
    __syncthreads();

    if (tid < CLS_) {
        float tot = 0.f;
#pragma unroll
        for (int v = 0; v < V_; v++) tot += cf[v];   // exact: integers < 2^24
        float acc = 0.f;
#pragma unroll
        for (int v = 0; v < V_; v++) acc += cf[v] * W[tid * V_ + v];
        out[b * CLS_ + tid] = acc / tot + bias[tid];
    }
}

extern "C" void kernel_launch(void* const* d_in, const int* in_sizes, int n_in,
                              void* d_out, int out_size) {
    const float* x    = (const float*)d_in[0];   // [B, N, 3] f32
    const float* W    = (const float*)d_in[1];   // [CLASSES, V] f32
    const float* bias = (const float*)d_in[2];   // [CLASSES] f32
    float* out = (float*)d_out;                  // [B, CLASSES] f32

    fused_voxel_kernel<<<dim3(CHUNKS_, B_), TPB_>>>(x, W, bias, out);
}